// round 1
// baseline (speedup 1.0000x reference)
#include <cuda_runtime.h>
#include <math.h>

// ---------------------------------------------------------------------------
// Problem constants
// ---------------------------------------------------------------------------
#define NIM   2
#define NOBJ  64
#define NPAIR 256
#define CD    512
#define HD    28
#define WD    28
#define HW    784           // 28*28
#define POOL  7
#define PQ    49            // 7*7
#define PDIM  4096
#define FLAT  25088         // 512*49
#define NREL  51

// ---------------------------------------------------------------------------
// Scratch (device globals; no dynamic allocation allowed)
// ---------------------------------------------------------------------------
__device__ float g_filt_dw[NOBJ * 4608];                     // (64, 512*9)
__device__ float g_filt_pw[(size_t)NOBJ * CD * CD];          // (64, 512, 512)  67 MB
__device__ float g_red[NIM * CD * HW];                       // (2, 512, 784)
__device__ float g_fd[(size_t)NOBJ * CD * HW];               // (64, 512, 784) 103 MB
__device__ float g_fp[(size_t)NOBJ * CD * HW];               // (64, 512, 784) 103 MB
__device__ float g_so[(size_t)NPAIR * 1024 * PQ];            // (256, 1024, 49) 51 MB
__device__ float g_rec[(size_t)NPAIR * FLAT];                // (256, 25088)   26 MB
__device__ float g_x1[NPAIR * PDIM];                         // (256, 4096)
__device__ float g_x2[NPAIR * PDIM];                         // (256, 4096)

// ---------------------------------------------------------------------------
// Tiled SGEMM, C = A(MxK) * B(NxK)^T + bias[n], optional relu
// 64x64 tile, 256 threads, 4x4 micro-tile, BK=16
// ---------------------------------------------------------------------------
#define BM 64
#define BN 64
#define BK 16

__global__ __launch_bounds__(256)
void gemm_nt_kernel(const float* __restrict__ A, const float* __restrict__ B,
                    const float* __restrict__ bias, float* __restrict__ C,
                    int M, int N, int K, int relu)
{
    __shared__ float As[BK][BM + 4];
    __shared__ float Bs[BK][BN + 4];
    int t  = threadIdx.x;
    int tx = t & 15, ty = t >> 4;
    int row0 = blockIdx.y * BM;
    int col0 = blockIdx.x * BN;

    float acc[4][4] = {};

    for (int kk = 0; kk < K; kk += BK) {
        #pragma unroll
        for (int i = 0; i < 4; i++) {
            int idx = t + 256 * i;
            int m = idx >> 4, k = idx & 15;
            float v = 0.f;
            if (row0 + m < M) v = A[(size_t)(row0 + m) * K + kk + k];
            As[k][m] = v;
        }
        #pragma unroll
        for (int i = 0; i < 4; i++) {
            int idx = t + 256 * i;
            int n = idx >> 4, k = idx & 15;
            float v = 0.f;
            if (col0 + n < N) v = B[(size_t)(col0 + n) * K + kk + k];
            Bs[k][n] = v;
        }
        __syncthreads();
        #pragma unroll
        for (int k = 0; k < BK; k++) {
            float a[4], b[4];
            #pragma unroll
            for (int i = 0; i < 4; i++) a[i] = As[k][ty * 4 + i];
            #pragma unroll
            for (int j = 0; j < 4; j++) b[j] = Bs[k][tx * 4 + j];
            #pragma unroll
            for (int i = 0; i < 4; i++)
                #pragma unroll
                for (int j = 0; j < 4; j++)
                    acc[i][j] += a[i] * b[j];
        }
        __syncthreads();
    }

    #pragma unroll
    for (int i = 0; i < 4; i++) {
        int m = row0 + ty * 4 + i;
        if (m >= M) continue;
        #pragma unroll
        for (int j = 0; j < 4; j++) {
            int n = col0 + tx * 4 + j;
            if (n >= N) continue;
            float v = acc[i][j] + (bias ? bias[n] : 0.f);
            if (relu) v = fmaxf(v, 0.f);
            C[(size_t)m * N + n] = v;
        }
    }
}

// ---------------------------------------------------------------------------
// Batched tiled SGEMM, C[b] = A[b](MxK) * B[b](KxN) + bias[m], optional relu
// aStride==0 => A shared across batch. bias indexed by row (m).
// ---------------------------------------------------------------------------
__global__ __launch_bounds__(256)
void gemm_nn_kernel(const float* __restrict__ A, long long aStride,
                    const float* __restrict__ B, long long bStride,
                    const float* __restrict__ bias, float* __restrict__ C,
                    long long cStride, int M, int N, int K, int relu)
{
    int bz = blockIdx.z;
    A += (size_t)bz * aStride;
    B += (size_t)bz * bStride;
    C += (size_t)bz * cStride;

    __shared__ float As[BK][BM + 4];
    __shared__ float Bs[BK][BN];
    int t  = threadIdx.x;
    int tx = t & 15, ty = t >> 4;
    int row0 = blockIdx.y * BM;
    int col0 = blockIdx.x * BN;

    float acc[4][4] = {};

    for (int kk = 0; kk < K; kk += BK) {
        #pragma unroll
        for (int i = 0; i < 4; i++) {
            int idx = t + 256 * i;
            int m = idx >> 4, k = idx & 15;
            float v = 0.f;
            if (row0 + m < M) v = A[(size_t)(row0 + m) * K + kk + k];
            As[k][m] = v;
        }
        #pragma unroll
        for (int i = 0; i < 4; i++) {
            int idx = t + 256 * i;
            int k = idx >> 6, n = idx & 63;
            float v = 0.f;
            if (col0 + n < N) v = B[(size_t)(kk + k) * N + col0 + n];
            Bs[k][n] = v;
        }
        __syncthreads();
        #pragma unroll
        for (int k = 0; k < BK; k++) {
            float a[4], b[4];
            #pragma unroll
            for (int i = 0; i < 4; i++) a[i] = As[k][ty * 4 + i];
            #pragma unroll
            for (int j = 0; j < 4; j++) b[j] = Bs[k][tx * 4 + j];
            #pragma unroll
            for (int i = 0; i < 4; i++)
                #pragma unroll
                for (int j = 0; j < 4; j++)
                    acc[i][j] += a[i] * b[j];
        }
        __syncthreads();
    }

    #pragma unroll
    for (int i = 0; i < 4; i++) {
        int m = row0 + ty * 4 + i;
        if (m >= M) continue;
        float bv = bias ? bias[m] : 0.f;
        #pragma unroll
        for (int j = 0; j < 4; j++) {
            int n = col0 + tx * 4 + j;
            if (n >= N) continue;
            float v = acc[i][j] + bv;
            if (relu) v = fmaxf(v, 0.f);
            C[(size_t)m * N + n] = v;
        }
    }
}

// ---------------------------------------------------------------------------
// Per-object depthwise 3x3 conv: fd[n,c] = conv3x3(red[im[n], c], filt_dw[n,c])
// One block per (n, c); channel cached in smem.
// ---------------------------------------------------------------------------
__global__ __launch_bounds__(256)
void dwconv_kernel(const float* __restrict__ rois)
{
    int nc = blockIdx.x;
    int n = nc >> 9, c = nc & 511;
    int im = (int)rois[n * 5];

    __shared__ float tile[HW];
    __shared__ float f[9];

    const float* src = g_red + ((size_t)im * CD + c) * HW;
    for (int i = threadIdx.x; i < HW; i += blockDim.x) tile[i] = src[i];
    if (threadIdx.x < 9) f[threadIdx.x] = g_filt_dw[(size_t)n * 4608 + c * 9 + threadIdx.x];
    __syncthreads();

    float* dst = g_fd + (size_t)nc * HW;
    for (int p = threadIdx.x; p < HW; p += blockDim.x) {
        int h = p / WD, w = p % WD;
        float s = 0.f;
        #pragma unroll
        for (int i = 0; i < 3; i++) {
            int hh = h + i - 1;
            if ((unsigned)hh >= HD) continue;
            #pragma unroll
            for (int j = 0; j < 3; j++) {
                int ww = w + j - 1;
                if ((unsigned)ww >= WD) continue;
                s += tile[hh * WD + ww] * f[i * 3 + j];
            }
        }
        dst[p] = s;
    }
}

// ---------------------------------------------------------------------------
// ROI align (single-sample bilinear per pooled cell) -> concatenated so buffer
// so[p, c, py, px]; c<512 uses sub pair-member, c>=512 uses obj.
// ---------------------------------------------------------------------------
__global__ __launch_bounds__(256)
void roialign_kernel(const float* __restrict__ rois, const int* __restrict__ rel_inds)
{
    long long tid = (long long)blockIdx.x * 256 + threadIdx.x;
    const long long total = (long long)NPAIR * 1024 * PQ;
    if (tid >= total) return;

    int q = (int)(tid % PQ);
    int c = (int)((tid / PQ) % 1024);
    int p = (int)(tid / (PQ * 1024));
    int py = q / POOL, px = q % POOL;

    int n  = (c < CD) ? rel_inds[p * 3 + 1] : rel_inds[p * 3 + 2];
    int ch = c & (CD - 1);

    const float* box = rois + n * 5 + 1;
    float b0 = box[0] * (1.f / 16.f), b1 = box[1] * (1.f / 16.f);
    float b2 = box[2] * (1.f / 16.f), b3 = box[3] * (1.f / 16.f);

    float gx = (px + 0.5f) / (float)POOL;
    float gy = (py + 0.5f) / (float)POOL;
    float x = fminf(fmaxf(b0 + gx * (b2 - b0), 0.f), (float)(WD - 1));
    float y = fminf(fmaxf(b1 + gy * (b3 - b1), 0.f), (float)(HD - 1));

    int x0 = (int)floorf(x), y0 = (int)floorf(y);
    int x1 = min(x0 + 1, WD - 1), y1 = min(y0 + 1, HD - 1);
    float wx = x - (float)x0, wy = y - (float)y0;

    const float* f = g_fp + ((size_t)n * CD + ch) * HW;
    float v = f[y0 * WD + x0] * (1.f - wy) * (1.f - wx)
            + f[y0 * WD + x1] * (1.f - wy) * wx
            + f[y1 * WD + x0] * wy * (1.f - wx)
            + f[y1 * WD + x1] * wy * wx;
    g_so[tid] = v;
}

// ---------------------------------------------------------------------------
// Launch
// ---------------------------------------------------------------------------
static inline int ceil_div(int a, int b) { return (a + b - 1) / b; }

extern "C" void kernel_launch(void* const* d_in, const int* in_sizes, int n_in,
                              void* d_out, int out_size)
{
    const float* fmaps    = (const float*)d_in[0];
    const float* rois     = (const float*)d_in[1];
    const int*   rel_inds = (const int*)  d_in[2];
    const float* feats    = (const float*)d_in[3];
    const float* w_dw  = (const float*)d_in[4];
    const float* b_dw  = (const float*)d_in[5];
    const float* w_pw  = (const float*)d_in[6];
    const float* b_pw  = (const float*)d_in[7];
    const float* w_red = (const float*)d_in[8];
    const float* b_red = (const float*)d_in[9];
    const float* w_rec = (const float*)d_in[10];
    const float* b_rec = (const float*)d_in[11];
    const float* w_fc1 = (const float*)d_in[12];
    const float* b_fc1 = (const float*)d_in[13];
    const float* w_fc2 = (const float*)d_in[14];
    const float* b_fc2 = (const float*)d_in[15];
    const float* w_rel = (const float*)d_in[16];
    const float* b_rel = (const float*)d_in[17];
    float* out = (float*)d_out;

    float *p_filt_dw, *p_filt_pw, *p_red, *p_fd, *p_fp, *p_so, *p_rec, *p_x1, *p_x2;
    cudaGetSymbolAddress((void**)&p_filt_dw, g_filt_dw);
    cudaGetSymbolAddress((void**)&p_filt_pw, g_filt_pw);
    cudaGetSymbolAddress((void**)&p_red,     g_red);
    cudaGetSymbolAddress((void**)&p_fd,      g_fd);
    cudaGetSymbolAddress((void**)&p_fp,      g_fp);
    cudaGetSymbolAddress((void**)&p_so,      g_so);
    cudaGetSymbolAddress((void**)&p_rec,     g_rec);
    cudaGetSymbolAddress((void**)&p_x1,      g_x1);
    cudaGetSymbolAddress((void**)&p_x2,      g_x2);

    // 1) filt_dw = feats @ w_dw^T + b_dw           (64 x 4608, K=512)
    gemm_nt_kernel<<<dim3(ceil_div(4608, BN), ceil_div(NOBJ, BM)), 256>>>(
        feats, w_dw, b_dw, p_filt_dw, NOBJ, 4608, CD, 0);

    // 2) filt_pw = feats @ w_pw^T + b_pw           (64 x 262144, K=512)
    gemm_nt_kernel<<<dim3(ceil_div(CD * CD, BN), ceil_div(NOBJ, BM)), 256>>>(
        feats, w_pw, b_pw, p_filt_pw, NOBJ, CD * CD, CD, 0);

    // 3) red[b] = relu(w_red @ fmaps[b] + b_red)   (batch=2, 512x784, K=512)
    gemm_nn_kernel<<<dim3(ceil_div(HW, BN), ceil_div(CD, BM), NIM), 256>>>(
        w_red, 0, fmaps, (long long)CD * HW, b_red, p_red, (long long)CD * HW,
        CD, HW, CD, 1);

    // 4) depthwise 3x3 with per-object filters
    dwconv_kernel<<<NOBJ * CD, 256>>>(rois);

    // 5) fp[n] = relu(filt_pw[n] @ fd[n])          (batch=64, 512x784, K=512)
    gemm_nn_kernel<<<dim3(ceil_div(HW, BN), ceil_div(CD, BM), NOBJ), 256>>>(
        p_filt_pw, (long long)CD * CD, p_fd, (long long)CD * HW, nullptr,
        p_fp, (long long)CD * HW, CD, HW, CD, 1);

    // 6) ROI align -> so (256, 1024, 49)
    {
        long long total = (long long)NPAIR * 1024 * PQ;
        roialign_kernel<<<(unsigned)((total + 255) / 256), 256>>>(rois, rel_inds);
    }

    // 7) rec[p] = w_rec @ so[p] + b_rec            (batch=256, 512x49, K=1024)
    gemm_nn_kernel<<<dim3(1, ceil_div(CD, BM), NPAIR), 256>>>(
        w_rec, 0, p_so, (long long)1024 * PQ, b_rec, p_rec, (long long)CD * PQ,
        CD, PQ, 1024, 0);

    // 8) x1 = relu(rec @ w_fc1^T + b_fc1)          (256 x 4096, K=25088)
    gemm_nt_kernel<<<dim3(ceil_div(PDIM, BN), ceil_div(NPAIR, BM)), 256>>>(
        p_rec, w_fc1, b_fc1, p_x1, NPAIR, PDIM, FLAT, 1);

    // 9) x2 = x1 @ w_fc2^T + b_fc2                 (256 x 4096, K=4096)
    gemm_nt_kernel<<<dim3(ceil_div(PDIM, BN), ceil_div(NPAIR, BM)), 256>>>(
        p_x1, w_fc2, b_fc2, p_x2, NPAIR, PDIM, PDIM, 0);

    // 10) out = x2 @ w_rel^T + b_rel               (256 x 51, K=4096)
    gemm_nt_kernel<<<dim3(ceil_div(NREL, BN), ceil_div(NPAIR, BM)), 256>>>(
        p_x2, w_rel, b_rel, out, NPAIR, NREL, PDIM, 0);
}

// round 3
// speedup vs baseline: 2.8000x; 2.8000x over previous
#include <cuda_runtime.h>
#include <math.h>

// ---------------------------------------------------------------------------
// Problem constants
// ---------------------------------------------------------------------------
#define NIM   2
#define NOBJ  64
#define NPAIR 256
#define CD    512
#define HD    28
#define WD    28
#define HW    784
#define POOL  7
#define PQ    49
#define PDIM  4096
#define FLAT  25088
#define NREL  51
#define KSPLIT 4
#define KCHUNK (FLAT / KSPLIT)   // 6272

// ---------------------------------------------------------------------------
// Scratch (device globals)
// ---------------------------------------------------------------------------
__device__ float g_filt_dw[NOBJ * 4608];
__device__ float g_filt_pw[(size_t)NOBJ * CD * CD];
__device__ float g_red[NIM * CD * HW];
__device__ float g_fd[(size_t)NOBJ * CD * HW];
__device__ float g_fp[(size_t)NOBJ * CD * HW];
__device__ float g_pooled[(size_t)NOBJ * CD * PQ];      // (64, 512, 49)
__device__ float g_A[(size_t)2 * NOBJ * FLAT];          // (128, 25088) A_s rows 0..63, A_o rows 64..127
__device__ float g_U[(size_t)KSPLIT * 2 * NOBJ * PDIM]; // (4, 128, 4096)
__device__ float g_x1[NPAIR * PDIM];
__device__ float g_x2[NPAIR * PDIM];

// ---------------------------------------------------------------------------
// tf32 helpers (3xTF32 decomposition for ~fp32 accuracy)
// ---------------------------------------------------------------------------
__device__ __forceinline__ unsigned f2tf32(float x) {
    unsigned r;
    asm("cvt.rna.tf32.f32 %0, %1;" : "=r"(r) : "f"(x));
    return r;
}
__device__ __forceinline__ void split_tf32(float v, unsigned& hi, unsigned& lo) {
    hi = f2tf32(v);
    lo = f2tf32(v - __uint_as_float(hi));
}
__device__ __forceinline__ void mma_tf32(float* d, const unsigned* a, const unsigned* b) {
    asm volatile(
        "mma.sync.aligned.m16n8k8.row.col.f32.tf32.tf32.f32 "
        "{%0,%1,%2,%3}, {%4,%5,%6,%7}, {%8,%9}, {%0,%1,%2,%3};"
        : "+f"(d[0]), "+f"(d[1]), "+f"(d[2]), "+f"(d[3])
        : "r"(a[0]), "r"(a[1]), "r"(a[2]), "r"(a[3]), "r"(b[0]), "r"(b[1]));
}

#define BM 64
#define BN 64
#define BK 16

// ---------------------------------------------------------------------------
// NT GEMM (tensor core): C = A(MxK,row,lda) * B(NxK,row,ldb)^T [+bias[n]] [relu]
// blockIdx.z = split-K index: A+=z*Kloop, B+=z*Kloop, C+=z*M*N
// 128 threads, 4 warps (2x2), warp tile 32x32, mma m16n8k8 tf32 x3
// ---------------------------------------------------------------------------
__global__ __launch_bounds__(128)
void gemm_nt_tc(const float* __restrict__ A, long long lda,
                const float* __restrict__ B, long long ldb,
                const float* __restrict__ bias, float* __restrict__ C,
                int M, int N, int Kloop, int relu)
{
    int z = blockIdx.z;
    A += (size_t)z * Kloop;
    B += (size_t)z * Kloop;
    C += (size_t)z * M * N;

    __shared__ float As[BK][BM + 4];
    __shared__ float Bs[BK][BN + 4];

    const int t = threadIdx.x;
    const int lane = t & 31, warp = t >> 5;
    const int wm = warp >> 1, wn = warp & 1;
    const int row0 = blockIdx.y * BM;
    const int col0 = blockIdx.x * BN;
    const int r = lane >> 2, c = lane & 3;

    float acc[2][4][4] = {};

    for (int kk = 0; kk < Kloop; kk += BK) {
        #pragma unroll
        for (int i = 0; i < 2; i++) {
            int idx = t + 128 * i;
            int m = idx >> 2, kg = (idx & 3) * 4;
            float4 v = make_float4(0.f, 0.f, 0.f, 0.f);
            if (row0 + m < M)
                v = *(const float4*)&A[(size_t)(row0 + m) * lda + kk + kg];
            As[kg + 0][m] = v.x; As[kg + 1][m] = v.y;
            As[kg + 2][m] = v.z; As[kg + 3][m] = v.w;
        }
        #pragma unroll
        for (int i = 0; i < 2; i++) {
            int idx = t + 128 * i;
            int n = idx >> 2, kg = (idx & 3) * 4;
            float4 v = make_float4(0.f, 0.f, 0.f, 0.f);
            if (col0 + n < N)
                v = *(const float4*)&B[(size_t)(col0 + n) * ldb + kk + kg];
            Bs[kg + 0][n] = v.x; Bs[kg + 1][n] = v.y;
            Bs[kg + 2][n] = v.z; Bs[kg + 3][n] = v.w;
        }
        __syncthreads();

        #pragma unroll
        for (int ks = 0; ks < BK; ks += 8) {
            unsigned ah[2][4], al[2][4], bh[4][2], bl[4][2];
            #pragma unroll
            for (int mt = 0; mt < 2; mt++) {
                int rb = wm * 32 + mt * 16 + r;
                split_tf32(As[ks + c    ][rb    ], ah[mt][0], al[mt][0]);
                split_tf32(As[ks + c    ][rb + 8], ah[mt][1], al[mt][1]);
                split_tf32(As[ks + c + 4][rb    ], ah[mt][2], al[mt][2]);
                split_tf32(As[ks + c + 4][rb + 8], ah[mt][3], al[mt][3]);
            }
            #pragma unroll
            for (int nt = 0; nt < 4; nt++) {
                int cb = wn * 32 + nt * 8 + r;
                split_tf32(Bs[ks + c    ][cb], bh[nt][0], bl[nt][0]);
                split_tf32(Bs[ks + c + 4][cb], bh[nt][1], bl[nt][1]);
            }
            #pragma unroll
            for (int mt = 0; mt < 2; mt++)
                #pragma unroll
                for (int nt = 0; nt < 4; nt++) {
                    mma_tf32(acc[mt][nt], al[mt], bh[nt]);
                    mma_tf32(acc[mt][nt], ah[mt], bl[nt]);
                    mma_tf32(acc[mt][nt], ah[mt], bh[nt]);
                }
        }
        __syncthreads();
    }

    #pragma unroll
    for (int mt = 0; mt < 2; mt++) {
        #pragma unroll
        for (int nt = 0; nt < 4; nt++) {
            int rb = row0 + wm * 32 + mt * 16 + r;
            int cb = col0 + wn * 32 + nt * 8 + c * 2;
            #pragma unroll
            for (int e = 0; e < 4; e++) {
                int rr = rb + (e >> 1) * 8;
                int cc = cb + (e & 1);
                if (rr < M && cc < N) {
                    float v = acc[mt][nt][e] + (bias ? bias[cc] : 0.f);
                    if (relu) v = fmaxf(v, 0.f);
                    C[(size_t)rr * N + cc] = v;
                }
            }
        }
    }
}

// ---------------------------------------------------------------------------
// Batched NN GEMM (tensor core): C[b] = A[b](MxK,lda) * B[b](KxN) [+bias[m]] [relu]
// aStride==0 => shared A. blockIdx.z = batch.
// ---------------------------------------------------------------------------
__global__ __launch_bounds__(128)
void gemm_nn_tc(const float* __restrict__ A, long long aStride, long long lda,
                const float* __restrict__ B, long long bStride,
                const float* __restrict__ bias, float* __restrict__ C,
                long long cStride, int M, int N, int K, int relu)
{
    int bz = blockIdx.z;
    A += (size_t)bz * aStride;
    B += (size_t)bz * bStride;
    C += (size_t)bz * cStride;

    __shared__ float As[BK][BM + 4];
    __shared__ float Bs[BK][BN + 4];

    const int t = threadIdx.x;
    const int lane = t & 31, warp = t >> 5;
    const int wm = warp >> 1, wn = warp & 1;
    const int row0 = blockIdx.y * BM;
    const int col0 = blockIdx.x * BN;
    const int r = lane >> 2, c = lane & 3;

    float acc[2][4][4] = {};

    for (int kk = 0; kk < K; kk += BK) {
        #pragma unroll
        for (int i = 0; i < 2; i++) {
            int idx = t + 128 * i;
            int m = idx >> 2, kg = (idx & 3) * 4;
            float4 v = make_float4(0.f, 0.f, 0.f, 0.f);
            if (row0 + m < M)
                v = *(const float4*)&A[(size_t)(row0 + m) * lda + kk + kg];
            As[kg + 0][m] = v.x; As[kg + 1][m] = v.y;
            As[kg + 2][m] = v.z; As[kg + 3][m] = v.w;
        }
        #pragma unroll
        for (int i = 0; i < 8; i++) {
            int idx = t + 128 * i;
            int k = idx >> 6, n = idx & 63;
            float v = 0.f;
            if (col0 + n < N) v = B[(size_t)(kk + k) * N + col0 + n];
            Bs[k][n] = v;
        }
        __syncthreads();

        #pragma unroll
        for (int ks = 0; ks < BK; ks += 8) {
            unsigned ah[2][4], al[2][4], bh[4][2], bl[4][2];
            #pragma unroll
            for (int mt = 0; mt < 2; mt++) {
                int rb = wm * 32 + mt * 16 + r;
                split_tf32(As[ks + c    ][rb    ], ah[mt][0], al[mt][0]);
                split_tf32(As[ks + c    ][rb + 8], ah[mt][1], al[mt][1]);
                split_tf32(As[ks + c + 4][rb    ], ah[mt][2], al[mt][2]);
                split_tf32(As[ks + c + 4][rb + 8], ah[mt][3], al[mt][3]);
            }
            #pragma unroll
            for (int nt = 0; nt < 4; nt++) {
                int cb = wn * 32 + nt * 8 + r;
                split_tf32(Bs[ks + c    ][cb], bh[nt][0], bl[nt][0]);
                split_tf32(Bs[ks + c + 4][cb], bh[nt][1], bl[nt][1]);
            }
            #pragma unroll
            for (int mt = 0; mt < 2; mt++)
                #pragma unroll
                for (int nt = 0; nt < 4; nt++) {
                    mma_tf32(acc[mt][nt], al[mt], bh[nt]);
                    mma_tf32(acc[mt][nt], ah[mt], bl[nt]);
                    mma_tf32(acc[mt][nt], ah[mt], bh[nt]);
                }
        }
        __syncthreads();
    }

    #pragma unroll
    for (int mt = 0; mt < 2; mt++) {
        #pragma unroll
        for (int nt = 0; nt < 4; nt++) {
            int rb = row0 + wm * 32 + mt * 16 + r;
            int cb = col0 + wn * 32 + nt * 8 + c * 2;
            #pragma unroll
            for (int e = 0; e < 4; e++) {
                int rr = rb + (e >> 1) * 8;
                int cc = cb + (e & 1);
                if (rr < M && cc < N) {
                    float v = acc[mt][nt][e] + (bias ? bias[rr] : 0.f);
                    if (relu) v = fmaxf(v, 0.f);
                    C[(size_t)rr * N + cc] = v;
                }
            }
        }
    }
}

// ---------------------------------------------------------------------------
// Per-object depthwise 3x3 conv
// ---------------------------------------------------------------------------
__global__ __launch_bounds__(256)
void dwconv_kernel(const float* __restrict__ rois)
{
    int nc = blockIdx.x;
    int n = nc >> 9, c = nc & 511;
    int im = (int)rois[n * 5];

    __shared__ float tile[HW];
    __shared__ float f[9];

    const float* src = g_red + ((size_t)im * CD + c) * HW;
    for (int i = threadIdx.x; i < HW; i += blockDim.x) tile[i] = src[i];
    if (threadIdx.x < 9) f[threadIdx.x] = g_filt_dw[(size_t)n * 4608 + c * 9 + threadIdx.x];
    __syncthreads();

    float* dst = g_fd + (size_t)nc * HW;
    for (int p = threadIdx.x; p < HW; p += blockDim.x) {
        int h = p / WD, w = p % WD;
        float s = 0.f;
        #pragma unroll
        for (int i = 0; i < 3; i++) {
            int hh = h + i - 1;
            if ((unsigned)hh >= HD) continue;
            #pragma unroll
            for (int j = 0; j < 3; j++) {
                int ww = w + j - 1;
                if ((unsigned)ww >= WD) continue;
                s += tile[hh * WD + ww] * f[i * 3 + j];
            }
        }
        dst[p] = s;
    }
}

// ---------------------------------------------------------------------------
// Per-OBJECT ROI align -> pooled (64, 512, 49)
// ---------------------------------------------------------------------------
__global__ __launch_bounds__(256)
void roialign_obj_kernel(const float* __restrict__ rois)
{
    int tid = blockIdx.x * 256 + threadIdx.x;
    const int total = NOBJ * CD * PQ;
    if (tid >= total) return;

    int q = tid % PQ;
    int ch = (tid / PQ) % CD;
    int n = tid / (PQ * CD);
    int py = q / POOL, px = q % POOL;

    const float* box = rois + n * 5 + 1;
    float b0 = box[0] * (1.f / 16.f), b1 = box[1] * (1.f / 16.f);
    float b2 = box[2] * (1.f / 16.f), b3 = box[3] * (1.f / 16.f);

    float gx = (px + 0.5f) / (float)POOL;
    float gy = (py + 0.5f) / (float)POOL;
    float x = fminf(fmaxf(b0 + gx * (b2 - b0), 0.f), (float)(WD - 1));
    float y = fminf(fmaxf(b1 + gy * (b3 - b1), 0.f), (float)(HD - 1));

    int x0 = (int)floorf(x), y0 = (int)floorf(y);
    int x1 = min(x0 + 1, WD - 1), y1 = min(y0 + 1, HD - 1);
    float wx = x - (float)x0, wy = y - (float)y0;

    const float* f = g_fp + ((size_t)n * CD + ch) * HW;
    float v = f[y0 * WD + x0] * (1.f - wy) * (1.f - wx)
            + f[y0 * WD + x1] * (1.f - wy) * wx
            + f[y1 * WD + x0] * wy * (1.f - wx)
            + f[y1 * WD + x1] * wy * wx;
    g_pooled[tid] = v;
}

// ---------------------------------------------------------------------------
// Pair combine: x1[p,j] = relu(b_fc1[j] + sum_s U[s][sub[p],j] + U[s][64+obj[p],j])
// ---------------------------------------------------------------------------
__global__ __launch_bounds__(256)
void pair_combine_kernel(const int* __restrict__ rel_inds,
                         const float* __restrict__ b_fc1)
{
    int idx = blockIdx.x * 256 + threadIdx.x;
    if (idx >= NPAIR * PDIM) return;
    int p = idx >> 12, j = idx & (PDIM - 1);
    int s = rel_inds[p * 3 + 1];
    int o = rel_inds[p * 3 + 2];

    float v = b_fc1[j];
    #pragma unroll
    for (int sp = 0; sp < KSPLIT; sp++) {
        const float* Us = g_U + (size_t)sp * 2 * NOBJ * PDIM;
        v += Us[(size_t)s * PDIM + j] + Us[(size_t)(NOBJ + o) * PDIM + j];
    }
    g_x1[idx] = fmaxf(v, 0.f);
}

// ---------------------------------------------------------------------------
// rel GEMM: out[p,r] = x2[p,:] . w_rel[r,:] + b_rel[r]   (warp per output)
// ---------------------------------------------------------------------------
__global__ __launch_bounds__(256)
void rel_kernel(const float* __restrict__ w_rel, const float* __restrict__ b_rel,
                float* __restrict__ out)
{
    int gid = blockIdx.x * 256 + threadIdx.x;
    int wid = gid >> 5, lane = gid & 31;
    if (wid >= NPAIR * NREL) return;
    int p = wid / NREL, rr = wid % NREL;

    const float4* xa = (const float4*)(g_x2 + (size_t)p * PDIM);
    const float4* wr = (const float4*)(w_rel + (size_t)rr * PDIM);
    float acc = 0.f;
    for (int i = lane; i < PDIM / 4; i += 32) {
        float4 a = xa[i], w = wr[i];
        acc += a.x * w.x + a.y * w.y + a.z * w.z + a.w * w.w;
    }
    #pragma unroll
    for (int s = 16; s > 0; s >>= 1)
        acc += __shfl_down_sync(0xffffffffu, acc, s);
    if (lane == 0) out[(size_t)p * NREL + rr] = acc + b_rel[rr];
}

// ---------------------------------------------------------------------------
// Launch
// ---------------------------------------------------------------------------
static inline int ceil_div(int a, int b) { return (a + b - 1) / b; }

extern "C" void kernel_launch(void* const* d_in, const int* in_sizes, int n_in,
                              void* d_out, int out_size)
{
    const float* fmaps    = (const float*)d_in[0];
    const float* rois     = (const float*)d_in[1];
    const int*   rel_inds = (const int*)  d_in[2];
    const float* feats    = (const float*)d_in[3];
    const float* w_dw  = (const float*)d_in[4];
    const float* b_dw  = (const float*)d_in[5];
    const float* w_pw  = (const float*)d_in[6];
    const float* b_pw  = (const float*)d_in[7];
    const float* w_red = (const float*)d_in[8];
    const float* b_red = (const float*)d_in[9];
    const float* w_rec = (const float*)d_in[10];
    const float* b_rec = (const float*)d_in[11];
    const float* w_fc1 = (const float*)d_in[12];
    const float* b_fc1 = (const float*)d_in[13];
    const float* w_fc2 = (const float*)d_in[14];
    const float* b_fc2 = (const float*)d_in[15];
    const float* w_rel = (const float*)d_in[16];
    const float* b_rel = (const float*)d_in[17];
    float* out = (float*)d_out;

    float *p_filt_dw, *p_filt_pw, *p_red, *p_fd, *p_fp, *p_pooled, *p_A, *p_U, *p_x1, *p_x2;
    cudaGetSymbolAddress((void**)&p_filt_dw, g_filt_dw);
    cudaGetSymbolAddress((void**)&p_filt_pw, g_filt_pw);
    cudaGetSymbolAddress((void**)&p_red,     g_red);
    cudaGetSymbolAddress((void**)&p_fd,      g_fd);
    cudaGetSymbolAddress((void**)&p_fp,      g_fp);
    cudaGetSymbolAddress((void**)&p_pooled,  g_pooled);
    cudaGetSymbolAddress((void**)&p_A,       g_A);
    cudaGetSymbolAddress((void**)&p_U,       g_U);
    cudaGetSymbolAddress((void**)&p_x1,      g_x1);
    cudaGetSymbolAddress((void**)&p_x2,      g_x2);

    // 1) filt_dw = feats @ w_dw^T + b_dw  (64 x 4608, K=512)
    gemm_nt_tc<<<dim3(ceil_div(4608, BN), 1, 1), 128>>>(
        feats, CD, w_dw, CD, b_dw, p_filt_dw, NOBJ, 4608, CD, 0);

    // 2) filt_pw = feats @ w_pw^T + b_pw  (64 x 262144, K=512)
    gemm_nt_tc<<<dim3(ceil_div(CD * CD, BN), 1, 1), 128>>>(
        feats, CD, w_pw, CD, b_pw, p_filt_pw, NOBJ, CD * CD, CD, 0);

    // 3) red[b] = relu(w_red @ fmaps[b] + b_red)  (batch 2, 512x784, K=512)
    gemm_nn_tc<<<dim3(ceil_div(HW, BN), ceil_div(CD, BM), NIM), 128>>>(
        w_red, 0, CD, fmaps, (long long)CD * HW, b_red, p_red,
        (long long)CD * HW, CD, HW, CD, 1);

    // 4) depthwise 3x3
    dwconv_kernel<<<NOBJ * CD, 256>>>(rois);

    // 5) fp[n] = relu(filt_pw[n] @ fd[n])  (batch 64, 512x784, K=512)
    gemm_nn_tc<<<dim3(ceil_div(HW, BN), ceil_div(CD, BM), NOBJ), 128>>>(
        p_filt_pw, (long long)CD * CD, CD, p_fd, (long long)CD * HW, nullptr,
        p_fp, (long long)CD * HW, CD, HW, CD, 1);

    // 6) per-object ROI align -> pooled (64, 512, 49)
    roialign_obj_kernel<<<ceil_div(NOBJ * CD * PQ, 256), 256>>>(rois);

    // 7) A_s[n] = w_rec[:, :512] @ pooled[n] + b_rec   (batch 64, 512x49, K=512)
    gemm_nn_tc<<<dim3(1, ceil_div(CD, BM), NOBJ), 128>>>(
        w_rec, 0, 2 * CD, p_pooled, (long long)CD * PQ, b_rec, p_A,
        (long long)FLAT, CD, PQ, CD, 0);

    // 8) A_o[n] = w_rec[:, 512:] @ pooled[n]
    gemm_nn_tc<<<dim3(1, ceil_div(CD, BM), NOBJ), 128>>>(
        w_rec + CD, 0, 2 * CD, p_pooled, (long long)CD * PQ, nullptr,
        p_A + (size_t)NOBJ * FLAT, (long long)FLAT, CD, PQ, CD, 0);

    // 9) U[s] = A_flat @ w_fc1^T   (128 x 4096, K=25088, split-K=4)
    gemm_nt_tc<<<dim3(PDIM / BN, 2, KSPLIT), 128>>>(
        p_A, FLAT, w_fc1, FLAT, nullptr, p_U, 2 * NOBJ, PDIM, KCHUNK, 0);

    // 10) x1[p] = relu(U_s[sub] + U_o[obj] + b_fc1)
    pair_combine_kernel<<<ceil_div(NPAIR * PDIM, 256), 256>>>(rel_inds, b_fc1);

    // 11) x2 = x1 @ w_fc2^T + b_fc2   (256 x 4096, K=4096)
    gemm_nt_tc<<<dim3(PDIM / BN, NPAIR / BM, 1), 128>>>(
        p_x1, PDIM, w_fc2, PDIM, b_fc2, p_x2, NPAIR, PDIM, PDIM, 0);

    // 12) out = x2 @ w_rel^T + b_rel   (256 x 51, K=4096)
    rel_kernel<<<ceil_div(NPAIR * NREL * 32, 256), 256>>>(w_rel, b_rel, out);
}